// round 5
// baseline (speedup 1.0000x reference)
#include <cuda_runtime.h>

#define NPTS 8192
#define CIN  256
#define NSAMP 16
#define HDIM 32

// ---------------- scratch (device globals; no allocation) ----------------
__device__ float4 g_p4[NPTS];               // (x, y, z, |p|^2)
__device__ int   g_idx[NPTS * NSAMP];
__device__ float g_xq[NPTS * CIN];
__device__ float g_xk[NPTS * CIN];
__device__ float g_xv[NPTS * CIN];
__device__ float g_w2t[HDIM * HDIM];        // w_l2_w transposed: [h][k]
__device__ float g_bn1s[CIN], g_bn1h[CIN];
__device__ float g_bn2s[HDIM], g_bn2h[HDIM];

// ---------------- pack points + squared norms ----------------
__global__ void pack_kernel(const float* __restrict__ p) {
    int i = blockIdx.x * blockDim.x + threadIdx.x;
    if (i < NPTS) {
        float x = p[3 * i], y = p[3 * i + 1], z = p[3 * i + 2];
        g_p4[i] = make_float4(x, y, z, fmaf(z, z, fmaf(y, y, x * x)));
    }
}

// ---------------- weight prep: w2 transpose + folded BN affine ----------------
__global__ void prep_kernel(const float* __restrict__ w_l2_w,
                            const float* __restrict__ g1, const float* __restrict__ b1,
                            const float* __restrict__ m1, const float* __restrict__ v1,
                            const float* __restrict__ g2, const float* __restrict__ b2,
                            const float* __restrict__ m2, const float* __restrict__ v2) {
    int tid = threadIdx.x;
    for (int e = tid; e < HDIM * HDIM; e += blockDim.x) {
        int h = e >> 5, k = e & 31;
        g_w2t[e] = w_l2_w[k * HDIM + h];
    }
    if (tid < CIN) {
        float s = g1[tid] * rsqrtf(v1[tid] + 1e-5f);
        g_bn1s[tid] = s;
        g_bn1h[tid] = b1[tid] - m1[tid] * s;
    }
    if (tid < HDIM) {
        float s = g2[tid] * rsqrtf(v2[tid] + 1e-5f);
        g_bn2s[tid] = s;
        g_bn2h[tid] = b2[tid] - m2[tid] * s;
    }
}

// ---------------- KNN: warp per query, unsorted top-16 + tracked max ----------------
#define KTS 512
__global__ __launch_bounds__(128) void knn_kernel() {
    __shared__ float4 spt[KTS];          // 8KB
    __shared__ float md[4 * 512];        // 8KB
    __shared__ int   mi[4 * 512];        // 8KB

    int tid = threadIdx.x, lane = tid & 31, warp = tid >> 5;
    int q = blockIdx.x * 4 + warp;
    float4 qp = g_p4[q];
    float qx = qp.x, qy = qp.y, qz = qp.z, qsq = qp.w;

    const float FINF = 3.402823466e+38f;
    float ld_[16];
    int   li_[16];
#pragma unroll
    for (int k = 0; k < 16; ++k) { ld_[k] = FINF; li_[k] = 0x7fffffff; }

    float maxv = FINF;     // current max of this lane's 16-list
    float cutoff = FINF;   // safe warp-level prune threshold (monotone non-increasing)

    for (int base = 0; base < NPTS; base += KTS) {
        __syncthreads();
        for (int i = tid; i < KTS; i += 128) spt[i] = g_p4[base + i];
        __syncthreads();

        for (int i = lane; i < KTS; i += 32) {
            float4 t = spt[i];
            float dot = fmaf(qz, t.z, fmaf(qy, t.y, qx * t.x));
            float d = fmaf(-2.f, dot, qsq + t.w);
            // tie-safe drop: only strictly-above-cutoff candidates pruned
            if (d <= cutoff && d < maxv) {
                bool done = false;
#pragma unroll
                for (int m = 0; m < 16; ++m) {
                    if (!done && ld_[m] == maxv) { ld_[m] = d; li_[m] = base + i; done = true; }
                }
                maxv = ld_[0];
#pragma unroll
                for (int m = 1; m < 16; ++m) maxv = fmaxf(maxv, ld_[m]);
            }
        }

        // c2 = min over lanes of the lane's 16th-best: that lane permanently
        // holds 16 elements <= c2.
        float c2 = maxv;
#pragma unroll
        for (int off = 16; off; off >>= 1)
            c2 = fminf(c2, __shfl_xor_sync(0xffffffffu, c2, off));

        if (base == 0) {
            // c1 = 16th smallest of the 32 per-lane minima (expensive; once).
            float mv = ld_[0];
#pragma unroll
            for (int m = 1; m < 16; ++m) mv = fminf(mv, ld_[m]);
            bool alive = true;
            float T = FINF;
#pragma unroll
            for (int r = 0; r < 16; ++r) {
                float v = alive ? mv : FINF;
#pragma unroll
                for (int off = 16; off; off >>= 1)
                    v = fminf(v, __shfl_xor_sync(0xffffffffu, v, off));
                T = v;
                if (alive && mv == v) alive = false;
            }
            cutoff = fminf(T, c2);
        } else {
            // lists only improve -> stale cutoff remains safe; tighten with c2
            cutoff = fminf(cutoff, c2);
        }
    }

    // sort the lane's 16 registers ascending by value (static network)
#pragma unroll
    for (int i = 0; i < 15; ++i)
#pragma unroll
        for (int j = 0; j < 15 - i; ++j) {
            if (ld_[j] > ld_[j + 1]) {
                float td = ld_[j]; ld_[j] = ld_[j + 1]; ld_[j + 1] = td;
                int ti = li_[j]; li_[j] = li_[j + 1]; li_[j + 1] = ti;
            }
        }

    // dump per-lane sorted lists, then 16-round warp merge
    int mb = warp * 512 + lane * 16;
#pragma unroll
    for (int k = 0; k < 16; ++k) { md[mb + k] = ld_[k]; mi[mb + k] = li_[k]; }
    __syncwarp();

    int ptr = 0;
    for (int r = 0; r < 16; ++r) {
        float bd; int bi;
        if (ptr < 16) { bd = md[mb + ptr]; bi = mi[mb + ptr]; }
        else          { bd = FINF;         bi = 0x7fffffff; }
        float vd = bd; int vi = bi;
#pragma unroll
        for (int off = 16; off; off >>= 1) {
            float od = __shfl_xor_sync(0xffffffffu, vd, off);
            int   oi = __shfl_xor_sync(0xffffffffu, vi, off);
            if (od < vd || (od == vd && oi < vi)) { vd = od; vi = oi; }
        }
        if (ptr < 16 && bd == vd && bi == vi) ptr++;
        if (lane == 0) g_idx[q * NSAMP + r] = vi;
    }
}

// ---------------- QKV SGEMM: 128x128x8 tiles, 8x8/thread, double buffered ----------------
__global__ __launch_bounds__(256) void qkv_gemm(
    const float* __restrict__ x,
    const float* __restrict__ w_q, const float* __restrict__ b_q,
    const float* __restrict__ w_k, const float* __restrict__ b_k,
    const float* __restrict__ w_v, const float* __restrict__ b_v) {

    const int BM = 128, BN = 128, BK = 8, TM = 8, TN = 8;
    __shared__ float As[2][BK * BM];  // transposed
    __shared__ float Bs[2][BK * BN];

    const float* W; const float* bias; float* O;
    if (blockIdx.z == 0)      { W = w_q; bias = b_q; O = g_xq; }
    else if (blockIdx.z == 1) { W = w_k; bias = b_k; O = g_xk; }
    else                      { W = w_v; bias = b_v; O = g_xv; }

    int tid = threadIdx.x;
    int cRow = blockIdx.y, cCol = blockIdx.x;

    int innerRowA = tid >> 1, innerColA = tid & 1;          // 128 rows x 2 float4
    int innerRowB = tid >> 5, innerColB = tid & 31;         // 8 rows x 32 float4
    int threadCol = tid & 15, threadRow = tid >> 4;

    const float* Aptr = &x[(cRow * BM + innerRowA) * CIN + innerColA * 4];
    const float* Bptr = &W[innerRowB * CIN + cCol * BN + innerColB * 4];

    float acc[TM][TN];
#pragma unroll
    for (int i = 0; i < TM; ++i)
#pragma unroll
        for (int j = 0; j < TN; ++j) acc[i][j] = 0.f;

    float regM[TM], regN[TN];

    // prologue: tile 0 into buffer 0
    {
        float4 tA = *reinterpret_cast<const float4*>(Aptr);
        float4 tB = *reinterpret_cast<const float4*>(Bptr);
        As[0][(innerColA * 4 + 0) * BM + innerRowA] = tA.x;
        As[0][(innerColA * 4 + 1) * BM + innerRowA] = tA.y;
        As[0][(innerColA * 4 + 2) * BM + innerRowA] = tA.z;
        As[0][(innerColA * 4 + 3) * BM + innerRowA] = tA.w;
        *reinterpret_cast<float4*>(&Bs[0][innerRowB * BN + innerColB * 4]) = tB;
    }
    __syncthreads();

    int buf = 0;
#pragma unroll 2
    for (int k0 = 0; k0 < CIN - BK; k0 += BK) {
        float4 nA = *reinterpret_cast<const float4*>(Aptr + k0 + BK);
        float4 nB = *reinterpret_cast<const float4*>(Bptr + (k0 + BK) * CIN);

#pragma unroll
        for (int k = 0; k < BK; ++k) {
#pragma unroll
            for (int i = 0; i < TM; i += 4)
                *reinterpret_cast<float4*>(&regM[i]) =
                    *reinterpret_cast<float4*>(&As[buf][k * BM + threadRow * TM + i]);
#pragma unroll
            for (int j = 0; j < TN; j += 4)
                *reinterpret_cast<float4*>(&regN[j]) =
                    *reinterpret_cast<float4*>(&Bs[buf][k * BN + threadCol * TN + j]);
#pragma unroll
            for (int i = 0; i < TM; ++i)
#pragma unroll
                for (int j = 0; j < TN; ++j)
                    acc[i][j] = fmaf(regM[i], regN[j], acc[i][j]);
        }

        int nb = buf ^ 1;
        As[nb][(innerColA * 4 + 0) * BM + innerRowA] = nA.x;
        As[nb][(innerColA * 4 + 1) * BM + innerRowA] = nA.y;
        As[nb][(innerColA * 4 + 2) * BM + innerRowA] = nA.z;
        As[nb][(innerColA * 4 + 3) * BM + innerRowA] = nA.w;
        *reinterpret_cast<float4*>(&Bs[nb][innerRowB * BN + innerColB * 4]) = nB;
        __syncthreads();
        buf = nb;
    }

    // last tile
#pragma unroll
    for (int k = 0; k < BK; ++k) {
#pragma unroll
        for (int i = 0; i < TM; i += 4)
            *reinterpret_cast<float4*>(&regM[i]) =
                *reinterpret_cast<float4*>(&As[buf][k * BM + threadRow * TM + i]);
#pragma unroll
        for (int j = 0; j < TN; j += 4)
            *reinterpret_cast<float4*>(&regN[j]) =
                *reinterpret_cast<float4*>(&Bs[buf][k * BN + threadCol * TN + j]);
#pragma unroll
        for (int i = 0; i < TM; ++i)
#pragma unroll
            for (int j = 0; j < TN; ++j)
                acc[i][j] = fmaf(regM[i], regN[j], acc[i][j]);
    }

    int col0 = cCol * BN + threadCol * TN;
    float breg[TN];
#pragma unroll
    for (int j = 0; j < TN; ++j) breg[j] = bias[col0 + j];

#pragma unroll
    for (int i = 0; i < TM; ++i) {
        int row = cRow * BM + threadRow * TM + i;
        float4 v0 = make_float4(acc[i][0] + breg[0], acc[i][1] + breg[1],
                                acc[i][2] + breg[2], acc[i][3] + breg[3]);
        float4 v1 = make_float4(acc[i][4] + breg[4], acc[i][5] + breg[5],
                                acc[i][6] + breg[6], acc[i][7] + breg[7]);
        *reinterpret_cast<float4*>(&O[row * CIN + col0])     = v0;
        *reinterpret_cast<float4*>(&O[row * CIN + col0 + 4]) = v1;
    }
}

// ---------------- fused per-point kernel (no s_pr: recompute in epilogue) ----------------
__global__ __launch_bounds__(256) void fused_kernel(
    const float* __restrict__ p,
    const float* __restrict__ p_w1, const float* __restrict__ p_b1,
    const float* __restrict__ p_bn_g, const float* __restrict__ p_bn_b,
    const float* __restrict__ p_bn_m, const float* __restrict__ p_bn_v,
    const float* __restrict__ p_w2, const float* __restrict__ p_b2,
    const float* __restrict__ w_l1_w, const float* __restrict__ w_l1_b,
    const float* __restrict__ w_l2_b,
    float* __restrict__ out) {

    __shared__ float s_xq[CIN];             // 1 KB
    __shared__ float s_a[NSAMP * CIN];      // 16 KB (reused as partials)
    __shared__ float s_u[NSAMP * HDIM];     // 2 KB
    __shared__ float s_w[NSAMP * 33];       // padded
    __shared__ int   s_idx[NSAMP];
    __shared__ float s_tv[NSAMP][3];
    __shared__ float s_pn[3];

    int n = blockIdx.x, tid = threadIdx.x, lane = tid & 31, warp = tid >> 5;

    if (tid < NSAMP) s_idx[tid] = g_idx[n * NSAMP + tid];
    if (tid < 3)     s_pn[tid] = p[n * 3 + tid];
    s_xq[tid] = g_xq[n * CIN + tid];
    __syncthreads();

    // pr hidden: Linear(3,3) -> BN -> ReLU, one thread per neighbor
    if (tid < NSAMP) {
        int j = s_idx[tid];
        float dx = p[j * 3]     - s_pn[0];
        float dy = p[j * 3 + 1] - s_pn[1];
        float dz = p[j * 3 + 2] - s_pn[2];
#pragma unroll
        for (int k = 0; k < 3; ++k) {
            float h = dx * p_w1[k] + dy * p_w1[3 + k] + dz * p_w1[6 + k] + p_b1[k];
            h = (h - p_bn_m[k]) * rsqrtf(p_bn_v[k] + 1e-5f) * p_bn_g[k] + p_bn_b[k];
            s_tv[tid][k] = fmaxf(h, 0.f);
        }
    }
    __syncthreads();

    // pr full (3->256) on the fly + gather xk + bn1/relu into s_a
    {
        float b1s = g_bn1s[tid], b1h = g_bn1h[tid];
        float xqv = s_xq[tid];
        float w20 = p_w2[tid], w21 = p_w2[256 + tid], w22 = p_w2[512 + tid];
        float pb2 = p_b2[tid];
#pragma unroll
        for (int r = 0; r < NSAMP; ++r) {
            float prv = fmaf(s_tv[r][2], w22, fmaf(s_tv[r][1], w21, fmaf(s_tv[r][0], w20, pb2)));
            float rqk = g_xk[s_idx[r] * CIN + tid] - xqv + prv;
            s_a[r * CIN + tid] = fmaxf(fmaf(rqk, b1s, b1h), 0.f);
        }
    }
    __syncthreads();

    // layer-1 matvec: warp owns 32 input channels (c = warp*32..+31), lane = output h.
    // w_l1_w read in original [c][h] layout -> coalesced LDG across lanes.
    float acc[NSAMP];
#pragma unroll
    for (int ns = 0; ns < NSAMP; ++ns) acc[ns] = 0.f;
    {
        int cbase = warp * 32;
#pragma unroll
        for (int g = 0; g < 8; ++g) {
            int c0 = cbase + g * 4;
            float wa = w_l1_w[(c0 + 0) * HDIM + lane];
            float wb = w_l1_w[(c0 + 1) * HDIM + lane];
            float wc = w_l1_w[(c0 + 2) * HDIM + lane];
            float wd = w_l1_w[(c0 + 3) * HDIM + lane];
#pragma unroll
            for (int ns = 0; ns < NSAMP; ++ns) {
                float4 av = *reinterpret_cast<const float4*>(&s_a[ns * CIN + c0]);
                acc[ns] = fmaf(av.x, wa, acc[ns]);
                acc[ns] = fmaf(av.y, wb, acc[ns]);
                acc[ns] = fmaf(av.z, wc, acc[ns]);
                acc[ns] = fmaf(av.w, wd, acc[ns]);
            }
        }
    }
    __syncthreads();   // all reads of s_a done before reuse as partial buffer

    float* s_part = s_a;   // 8*16*32 = 4096 floats, fits
#pragma unroll
    for (int ns = 0; ns < NSAMP; ++ns)
        s_part[(warp * NSAMP + ns) * 32 + lane] = acc[ns];
    __syncthreads();

    // reduce partials + bias + bn2 + relu
    for (int o = tid; o < NSAMP * HDIM; o += 256) {
        int ns = o >> 5, h = o & 31;
        float u = 0.f;
#pragma unroll
        for (int w8 = 0; w8 < 8; ++w8) u += s_part[(w8 * NSAMP + ns) * 32 + h];
        u += w_l1_b[h];
        s_u[ns * HDIM + h] = fmaxf(fmaf(u, g_bn2s[h], g_bn2h[h]), 0.f);
    }
    __syncthreads();

    // layer-2 (32x32) -> pre-softmax logits
    for (int o = tid; o < NSAMP * HDIM; o += 256) {
        int ns = o >> 5, h = o & 31;
        float accl = w_l2_b[h];
        const float* w2row = &g_w2t[h * HDIM];
#pragma unroll
        for (int g = 0; g < 8; ++g) {
            float4 wv = *reinterpret_cast<const float4*>(&w2row[g * 4]);
            float4 bv = *reinterpret_cast<const float4*>(&s_u[ns * HDIM + g * 4]);
            accl = fmaf(bv.x, wv.x, accl);
            accl = fmaf(bv.y, wv.y, accl);
            accl = fmaf(bv.z, wv.z, accl);
            accl = fmaf(bv.w, wv.w, accl);
        }
        s_w[ns * 33 + h] = accl;
    }
    __syncthreads();

    // softmax over neighbors (warp 0, lane = h)
    if (warp == 0) {
        float m = -3.402823466e+38f;
#pragma unroll
        for (int ns = 0; ns < NSAMP; ++ns) m = fmaxf(m, s_w[ns * 33 + lane]);
        float ev[NSAMP], sum = 0.f;
#pragma unroll
        for (int ns = 0; ns < NSAMP; ++ns) { ev[ns] = __expf(s_w[ns * 33 + lane] - m); sum += ev[ns]; }
        float inv = 1.f / sum;
#pragma unroll
        for (int ns = 0; ns < NSAMP; ++ns) s_w[ns * 33 + lane] = ev[ns] * inv;
    }
    __syncthreads();

    // aggregation: out[c] = sum_ns w[ns][c&31] * (xv[idx[ns]][c] + pr[ns][c]),
    // pr recomputed bit-identically from s_tv.
    {
        int i = tid & 31;
        float w20 = p_w2[tid], w21 = p_w2[256 + tid], w22 = p_w2[512 + tid];
        float pb2 = p_b2[tid];
        float accl = 0.f;
#pragma unroll
        for (int ns = 0; ns < NSAMP; ++ns) {
            float prv = fmaf(s_tv[ns][2], w22, fmaf(s_tv[ns][1], w21, fmaf(s_tv[ns][0], w20, pb2)));
            accl = fmaf(s_w[ns * 33 + i], g_xv[s_idx[ns] * CIN + tid] + prv, accl);
        }
        out[n * CIN + tid] = accl;
    }
}

// ---------------- launch ----------------
extern "C" void kernel_launch(void* const* d_in, const int* in_sizes, int n_in,
                              void* d_out, int out_size) {
    const float* p      = (const float*)d_in[0];
    const float* x      = (const float*)d_in[1];
    const float* w_q    = (const float*)d_in[2];
    const float* b_q    = (const float*)d_in[3];
    const float* w_k    = (const float*)d_in[4];
    const float* b_k    = (const float*)d_in[5];
    const float* w_v    = (const float*)d_in[6];
    const float* b_v    = (const float*)d_in[7];
    const float* p_w1   = (const float*)d_in[8];
    const float* p_b1   = (const float*)d_in[9];
    const float* p_bn_g = (const float*)d_in[10];
    const float* p_bn_b = (const float*)d_in[11];
    const float* p_bn_m = (const float*)d_in[12];
    const float* p_bn_v = (const float*)d_in[13];
    const float* p_w2   = (const float*)d_in[14];
    const float* p_b2   = (const float*)d_in[15];
    const float* bn1g   = (const float*)d_in[16];
    const float* bn1b   = (const float*)d_in[17];
    const float* bn1m   = (const float*)d_in[18];
    const float* bn1v   = (const float*)d_in[19];
    const float* w_l1_w = (const float*)d_in[20];
    const float* w_l1_b = (const float*)d_in[21];
    const float* bn2g   = (const float*)d_in[22];
    const float* bn2b   = (const float*)d_in[23];
    const float* bn2m   = (const float*)d_in[24];
    const float* bn2v   = (const float*)d_in[25];
    const float* w_l2_w = (const float*)d_in[26];
    const float* w_l2_b = (const float*)d_in[27];
    float* out = (float*)d_out;

    pack_kernel<<<(NPTS + 255) / 256, 256>>>(p);
    prep_kernel<<<1, 256>>>(w_l2_w, bn1g, bn1b, bn1m, bn1v, bn2g, bn2b, bn2m, bn2v);
    knn_kernel<<<NPTS / 4, 128>>>();
    qkv_gemm<<<dim3(CIN / 128, NPTS / 128, 3), 256>>>(x, w_q, b_q, w_k, b_k, w_v, b_v);
    fused_kernel<<<NPTS, 256>>>(p, p_w1, p_b1, p_bn_g, p_bn_b, p_bn_m, p_bn_v,
                                p_w2, p_b2, w_l1_w, w_l1_b, w_l2_b, out);
}

// round 6
// speedup vs baseline: 2.2072x; 2.2072x over previous
#include <cuda_runtime.h>

#define NPTS 8192
#define CIN  256
#define NSAMP 16
#define HDIM 32

// ---------------- scratch (device globals; no allocation) ----------------
__device__ float4 g_p4[NPTS];               // (x, y, z, |p|^2)
__device__ int   g_idx[NPTS * NSAMP];
__device__ float g_xq[NPTS * CIN];
__device__ float g_xk[NPTS * CIN];
__device__ float g_xv[NPTS * CIN];
__device__ float g_w2t[HDIM * HDIM];        // w_l2_w transposed: [h][k]
__device__ float g_bn1s[CIN], g_bn1h[CIN];
__device__ float g_bn2s[HDIM], g_bn2h[HDIM];

// ---------------- pack points + squared norms ----------------
__global__ void pack_kernel(const float* __restrict__ p) {
    int i = blockIdx.x * blockDim.x + threadIdx.x;
    if (i < NPTS) {
        float x = p[3 * i], y = p[3 * i + 1], z = p[3 * i + 2];
        g_p4[i] = make_float4(x, y, z, fmaf(z, z, fmaf(y, y, x * x)));
    }
}

// ---------------- weight prep: w2 transpose + folded BN affine ----------------
__global__ void prep_kernel(const float* __restrict__ w_l2_w,
                            const float* __restrict__ g1, const float* __restrict__ b1,
                            const float* __restrict__ m1, const float* __restrict__ v1,
                            const float* __restrict__ g2, const float* __restrict__ b2,
                            const float* __restrict__ m2, const float* __restrict__ v2) {
    int tid = threadIdx.x;
    for (int e = tid; e < HDIM * HDIM; e += blockDim.x) {
        int h = e >> 5, k = e & 31;
        g_w2t[e] = w_l2_w[k * HDIM + h];
    }
    if (tid < CIN) {
        float s = g1[tid] * rsqrtf(v1[tid] + 1e-5f);
        g_bn1s[tid] = s;
        g_bn1h[tid] = b1[tid] - m1[tid] * s;
    }
    if (tid < HDIM) {
        float s = g2[tid] * rsqrtf(v2[tid] + 1e-5f);
        g_bn2s[tid] = s;
        g_bn2h[tid] = b2[tid] - m2[tid] * s;
    }
}

// ---------------- QKV SGEMM: 128x128x8 tiles, 8x8/thread, double buffered ----------------
__global__ __launch_bounds__(256) void qkv_gemm(
    const float* __restrict__ x,
    const float* __restrict__ w_q, const float* __restrict__ b_q,
    const float* __restrict__ w_k, const float* __restrict__ b_k,
    const float* __restrict__ w_v, const float* __restrict__ b_v) {

    const int BM = 128, BN = 128, BK = 8, TM = 8, TN = 8;
    __shared__ float As[2][BK * BM];  // transposed
    __shared__ float Bs[2][BK * BN];

    const float* W; const float* bias; float* O;
    if (blockIdx.z == 0)      { W = w_q; bias = b_q; O = g_xq; }
    else if (blockIdx.z == 1) { W = w_k; bias = b_k; O = g_xk; }
    else                      { W = w_v; bias = b_v; O = g_xv; }

    int tid = threadIdx.x;
    int cRow = blockIdx.y, cCol = blockIdx.x;

    int innerRowA = tid >> 1, innerColA = tid & 1;          // 128 rows x 2 float4
    int innerRowB = tid >> 5, innerColB = tid & 31;         // 8 rows x 32 float4
    int threadCol = tid & 15, threadRow = tid >> 4;

    const float* Aptr = &x[(cRow * BM + innerRowA) * CIN + innerColA * 4];
    const float* Bptr = &W[innerRowB * CIN + cCol * BN + innerColB * 4];

    float acc[TM][TN];
#pragma unroll
    for (int i = 0; i < TM; ++i)
#pragma unroll
        for (int j = 0; j < TN; ++j) acc[i][j] = 0.f;

    float regM[TM], regN[TN];

    // prologue: tile 0 into buffer 0
    {
        float4 tA = *reinterpret_cast<const float4*>(Aptr);
        float4 tB = *reinterpret_cast<const float4*>(Bptr);
        As[0][(innerColA * 4 + 0) * BM + innerRowA] = tA.x;
        As[0][(innerColA * 4 + 1) * BM + innerRowA] = tA.y;
        As[0][(innerColA * 4 + 2) * BM + innerRowA] = tA.z;
        As[0][(innerColA * 4 + 3) * BM + innerRowA] = tA.w;
        *reinterpret_cast<float4*>(&Bs[0][innerRowB * BN + innerColB * 4]) = tB;
    }
    __syncthreads();

    int buf = 0;
#pragma unroll 2
    for (int k0 = 0; k0 < CIN - BK; k0 += BK) {
        float4 nA = *reinterpret_cast<const float4*>(Aptr + k0 + BK);
        float4 nB = *reinterpret_cast<const float4*>(Bptr + (k0 + BK) * CIN);

#pragma unroll
        for (int k = 0; k < BK; ++k) {
#pragma unroll
            for (int i = 0; i < TM; i += 4)
                *reinterpret_cast<float4*>(&regM[i]) =
                    *reinterpret_cast<float4*>(&As[buf][k * BM + threadRow * TM + i]);
#pragma unroll
            for (int j = 0; j < TN; j += 4)
                *reinterpret_cast<float4*>(&regN[j]) =
                    *reinterpret_cast<float4*>(&Bs[buf][k * BN + threadCol * TN + j]);
#pragma unroll
            for (int i = 0; i < TM; ++i)
#pragma unroll
                for (int j = 0; j < TN; ++j)
                    acc[i][j] = fmaf(regM[i], regN[j], acc[i][j]);
        }

        int nb = buf ^ 1;
        As[nb][(innerColA * 4 + 0) * BM + innerRowA] = nA.x;
        As[nb][(innerColA * 4 + 1) * BM + innerRowA] = nA.y;
        As[nb][(innerColA * 4 + 2) * BM + innerRowA] = nA.z;
        As[nb][(innerColA * 4 + 3) * BM + innerRowA] = nA.w;
        *reinterpret_cast<float4*>(&Bs[nb][innerRowB * BN + innerColB * 4]) = nB;
        __syncthreads();
        buf = nb;
    }

    // last tile
#pragma unroll
    for (int k = 0; k < BK; ++k) {
#pragma unroll
        for (int i = 0; i < TM; i += 4)
            *reinterpret_cast<float4*>(&regM[i]) =
                *reinterpret_cast<float4*>(&As[buf][k * BM + threadRow * TM + i]);
#pragma unroll
        for (int j = 0; j < TN; j += 4)
            *reinterpret_cast<float4*>(&regN[j]) =
                *reinterpret_cast<float4*>(&Bs[buf][k * BN + threadCol * TN + j]);
#pragma unroll
        for (int i = 0; i < TM; ++i)
#pragma unroll
            for (int j = 0; j < TN; ++j)
                acc[i][j] = fmaf(regM[i], regN[j], acc[i][j]);
    }

    int col0 = cCol * BN + threadCol * TN;
    float breg[TN];
#pragma unroll
    for (int j = 0; j < TN; ++j) breg[j] = bias[col0 + j];

#pragma unroll
    for (int i = 0; i < TM; ++i) {
        int row = cRow * BM + threadRow * TM + i;
        float4 v0 = make_float4(acc[i][0] + breg[0], acc[i][1] + breg[1],
                                acc[i][2] + breg[2], acc[i][3] + breg[3]);
        float4 v1 = make_float4(acc[i][4] + breg[4], acc[i][5] + breg[5],
                                acc[i][6] + breg[6], acc[i][7] + breg[7]);
        *reinterpret_cast<float4*>(&O[row * CIN + col0])     = v0;
        *reinterpret_cast<float4*>(&O[row * CIN + col0 + 4]) = v1;
    }
}

// ---------------- KNN: warp per query, top-16, tie-safe per-tile cutoff ----------------
#define KTS 512
__global__ __launch_bounds__(128) void knn_kernel() {
    __shared__ float4 spt[KTS];          // 8KB
    __shared__ float md[4 * 512];        // 8KB
    __shared__ int   mi[4 * 512];        // 8KB

    int tid = threadIdx.x, lane = tid & 31, warp = tid >> 5;
    int q = blockIdx.x * 4 + warp;
    float4 qp = g_p4[q];
    float qx = qp.x, qy = qp.y, qz = qp.z, qsq = qp.w;

    const float FINF = 3.402823466e+38f;
    float ld_[16];
    int   li_[16];
#pragma unroll
    for (int k = 0; k < 16; ++k) { ld_[k] = FINF; li_[k] = 0x7fffffff; }

    float cutoff = FINF;

    for (int base = 0; base < NPTS; base += KTS) {
        __syncthreads();
        for (int i = tid; i < KTS; i += 128) spt[i] = g_p4[base + i];
        __syncthreads();

        bool inserted = false;
        for (int i = lane; i < KTS; i += 32) {
            float4 t = spt[i];
            float dot = fmaf(qz, t.z, fmaf(qy, t.y, qx * t.x));
            float d = fmaf(-2.f, dot, qsq + t.w);
            // tie-safe: drop ONLY when strictly above cutoff (d <= cutoff keeps)
            if (d <= cutoff && d < ld_[15]) {
                inserted = true;
                ld_[15] = d; li_[15] = base + i;
#pragma unroll
                for (int m = 15; m > 0; --m) {
                    if (ld_[m] < ld_[m - 1]) {
                        float td = ld_[m]; ld_[m] = ld_[m - 1]; ld_[m - 1] = td;
                        int ti = li_[m]; li_[m] = li_[m - 1]; li_[m - 1] = ti;
                    }
                }
            }
        }

        // if no lane inserted this tile, lists (hence the bounds) are unchanged:
        // the previous cutoff remains exactly valid -> skip recompute.
        if (__ballot_sync(0xffffffffu, inserted) == 0u) continue;

        // --- recompute prune cutoff (safe bounds) ---
        // c2 = min over lanes of each lane's 16th-best: that lane holds 16
        //      elements <= c2, which persist in the union.
        float c2 = ld_[15];
#pragma unroll
        for (int off = 16; off; off >>= 1)
            c2 = fminf(c2, __shfl_xor_sync(0xffffffffu, c2, off));
        // c1 = 16th smallest of the 32 per-lane minima, via 16 rounds of
        //      warp min-reduce + deactivate-winner. On value ties multiple
        //      lanes deactivate together, which only makes c1 smaller (still
        //      safe: >=16 deactivated lanes each hold an element <= c1).
        {
            float mv = ld_[0];
            bool alive = true;
            float T = FINF;
#pragma unroll
            for (int r = 0; r < 16; ++r) {
                float v = alive ? mv : FINF;
#pragma unroll
                for (int off = 16; off; off >>= 1)
                    v = fminf(v, __shfl_xor_sync(0xffffffffu, v, off));
                T = v;
                if (alive && mv == v) alive = false;
            }
            cutoff = fminf(T, c2);
        }
    }

    // dump per-lane sorted lists, then 16-round warp merge
    int mb = warp * 512 + lane * 16;
#pragma unroll
    for (int k = 0; k < 16; ++k) { md[mb + k] = ld_[k]; mi[mb + k] = li_[k]; }
    __syncwarp();

    int ptr = 0;
    for (int r = 0; r < 16; ++r) {
        float bd; int bi;
        if (ptr < 16) { bd = md[mb + ptr]; bi = mi[mb + ptr]; }
        else          { bd = FINF;         bi = 0x7fffffff; }
        float vd = bd; int vi = bi;
#pragma unroll
        for (int off = 16; off; off >>= 1) {
            float od = __shfl_xor_sync(0xffffffffu, vd, off);
            int   oi = __shfl_xor_sync(0xffffffffu, vi, off);
            if (od < vd || (od == vd && oi < vi)) { vd = od; vi = oi; }
        }
        if (ptr < 16 && bd == vd && bi == vi) ptr++;
        if (lane == 0) g_idx[q * NSAMP + r] = vi;
    }
}

// ---------------- fused per-point kernel ----------------
__global__ __launch_bounds__(256) void fused_kernel(
    const float* __restrict__ p,
    const float* __restrict__ p_w1, const float* __restrict__ p_b1,
    const float* __restrict__ p_bn_g, const float* __restrict__ p_bn_b,
    const float* __restrict__ p_bn_m, const float* __restrict__ p_bn_v,
    const float* __restrict__ p_w2, const float* __restrict__ p_b2,
    const float* __restrict__ w_l1_w, const float* __restrict__ w_l1_b,
    const float* __restrict__ w_l2_b,
    float* __restrict__ out) {

    __shared__ float s_xq[CIN];             // 1 KB
    __shared__ float s_pr[NSAMP * CIN];     // 16 KB
    __shared__ float s_a[NSAMP * CIN];      // 16 KB (reused as partials)
    __shared__ float s_u[NSAMP * HDIM];     // 2 KB
    __shared__ float s_w[NSAMP * 33];       // padded
    __shared__ int   s_idx[NSAMP];
    __shared__ float s_tv[NSAMP][3];
    __shared__ float s_pn[3];

    int n = blockIdx.x, tid = threadIdx.x, lane = tid & 31, warp = tid >> 5;

    if (tid < NSAMP) s_idx[tid] = g_idx[n * NSAMP + tid];
    if (tid < 3)     s_pn[tid] = p[n * 3 + tid];
    s_xq[tid] = g_xq[n * CIN + tid];
    __syncthreads();

    // pr hidden: Linear(3,3) -> BN -> ReLU, one thread per neighbor
    if (tid < NSAMP) {
        int j = s_idx[tid];
        float dx = p[j * 3]     - s_pn[0];
        float dy = p[j * 3 + 1] - s_pn[1];
        float dz = p[j * 3 + 2] - s_pn[2];
#pragma unroll
        for (int k = 0; k < 3; ++k) {
            float h = dx * p_w1[k] + dy * p_w1[3 + k] + dz * p_w1[6 + k] + p_b1[k];
            h = (h - p_bn_m[k]) * rsqrtf(p_bn_v[k] + 1e-5f) * p_bn_g[k] + p_bn_b[k];
            s_tv[tid][k] = fmaxf(h, 0.f);
        }
    }
    __syncthreads();

    // pr full (3->256) + gather xk + bn1/relu into s_a
    {
        float b1s = g_bn1s[tid], b1h = g_bn1h[tid];
        float xqv = s_xq[tid];
        float w20 = p_w2[tid], w21 = p_w2[256 + tid], w22 = p_w2[512 + tid];
        float pb2 = p_b2[tid];
#pragma unroll
        for (int r = 0; r < NSAMP; ++r) {
            float prv = fmaf(s_tv[r][2], w22, fmaf(s_tv[r][1], w21, fmaf(s_tv[r][0], w20, pb2)));
            s_pr[r * CIN + tid] = prv;
            float rqk = g_xk[s_idx[r] * CIN + tid] - xqv + prv;
            s_a[r * CIN + tid] = fmaxf(fmaf(rqk, b1s, b1h), 0.f);
        }
    }
    __syncthreads();

    // layer-1 matvec: warp owns 32 input channels (c = warp*32..+31), lane = output h.
    // w_l1_w read in original [c][h] layout -> coalesced LDG across lanes.
    float acc[NSAMP];
#pragma unroll
    for (int ns = 0; ns < NSAMP; ++ns) acc[ns] = 0.f;
    {
        int cbase = warp * 32;
#pragma unroll
        for (int g = 0; g < 8; ++g) {
            int c0 = cbase + g * 4;
            float wa = w_l1_w[(c0 + 0) * HDIM + lane];
            float wb = w_l1_w[(c0 + 1) * HDIM + lane];
            float wc = w_l1_w[(c0 + 2) * HDIM + lane];
            float wd = w_l1_w[(c0 + 3) * HDIM + lane];
#pragma unroll
            for (int ns = 0; ns < NSAMP; ++ns) {
                float4 av = *reinterpret_cast<const float4*>(&s_a[ns * CIN + c0]);
                acc[ns] = fmaf(av.x, wa, acc[ns]);
                acc[ns] = fmaf(av.y, wb, acc[ns]);
                acc[ns] = fmaf(av.z, wc, acc[ns]);
                acc[ns] = fmaf(av.w, wd, acc[ns]);
            }
        }
    }
    __syncthreads();   // all reads of s_a done before reuse as partial buffer

    float* s_part = s_a;   // 8*16*32 = 4096 floats, fits exactly
#pragma unroll
    for (int ns = 0; ns < NSAMP; ++ns)
        s_part[(warp * NSAMP + ns) * 32 + lane] = acc[ns];
    __syncthreads();

    // reduce partials + bias + bn2 + relu
    for (int o = tid; o < NSAMP * HDIM; o += 256) {
        int ns = o >> 5, h = o & 31;
        float u = 0.f;
#pragma unroll
        for (int w8 = 0; w8 < 8; ++w8) u += s_part[(w8 * NSAMP + ns) * 32 + h];
        u += w_l1_b[h];
        s_u[ns * HDIM + h] = fmaxf(fmaf(u, g_bn2s[h], g_bn2h[h]), 0.f);
    }
    __syncthreads();

    // layer-2 (32x32) -> pre-softmax logits
    for (int o = tid; o < NSAMP * HDIM; o += 256) {
        int ns = o >> 5, h = o & 31;
        float accl = w_l2_b[h];
        const float* w2row = &g_w2t[h * HDIM];
#pragma unroll
        for (int g = 0; g < 8; ++g) {
            float4 wv = *reinterpret_cast<const float4*>(&w2row[g * 4]);
            float4 bv = *reinterpret_cast<const float4*>(&s_u[ns * HDIM + g * 4]);
            accl = fmaf(bv.x, wv.x, accl);
            accl = fmaf(bv.y, wv.y, accl);
            accl = fmaf(bv.z, wv.z, accl);
            accl = fmaf(bv.w, wv.w, accl);
        }
        s_w[ns * 33 + h] = accl;
    }
    __syncthreads();

    // softmax over neighbors (warp 0, lane = h)
    if (warp == 0) {
        float m = -3.402823466e+38f;
#pragma unroll
        for (int ns = 0; ns < NSAMP; ++ns) m = fmaxf(m, s_w[ns * 33 + lane]);
        float ev[NSAMP], sum = 0.f;
#pragma unroll
        for (int ns = 0; ns < NSAMP; ++ns) { ev[ns] = __expf(s_w[ns * 33 + lane] - m); sum += ev[ns]; }
        float inv = 1.f / sum;
#pragma unroll
        for (int ns = 0; ns < NSAMP; ++ns) s_w[ns * 33 + lane] = ev[ns] * inv;
    }
    __syncthreads();

    // aggregation: out[c] = sum_ns w[ns][c&31] * (xv[idx[ns]][c] + pr[ns][c])
    {
        int i = tid & 31;
        float accl = 0.f;
#pragma unroll
        for (int ns = 0; ns < NSAMP; ++ns)
            accl = fmaf(s_w[ns * 33 + i], g_xv[s_idx[ns] * CIN + tid] + s_pr[ns * CIN + tid], accl);
        out[n * CIN + tid] = accl;
    }
}

// ---------------- launch ----------------
extern "C" void kernel_launch(void* const* d_in, const int* in_sizes, int n_in,
                              void* d_out, int out_size) {
    const float* p      = (const float*)d_in[0];
    const float* x      = (const float*)d_in[1];
    const float* w_q    = (const float*)d_in[2];
    const float* b_q    = (const float*)d_in[3];
    const float* w_k    = (const float*)d_in[4];
    const float* b_k    = (const float*)d_in[5];
    const float* w_v    = (const float*)d_in[6];
    const float* b_v    = (const float*)d_in[7];
    const float* p_w1   = (const float*)d_in[8];
    const float* p_b1   = (const float*)d_in[9];
    const float* p_bn_g = (const float*)d_in[10];
    const float* p_bn_b = (const float*)d_in[11];
    const float* p_bn_m = (const float*)d_in[12];
    const float* p_bn_v = (const float*)d_in[13];
    const float* p_w2   = (const float*)d_in[14];
    const float* p_b2   = (const float*)d_in[15];
    const float* bn1g   = (const float*)d_in[16];
    const float* bn1b   = (const float*)d_in[17];
    const float* bn1m   = (const float*)d_in[18];
    const float* bn1v   = (const float*)d_in[19];
    const float* w_l1_w = (const float*)d_in[20];
    const float* w_l1_b = (const float*)d_in[21];
    const float* bn2g   = (const float*)d_in[22];
    const float* bn2b   = (const float*)d_in[23];
    const float* bn2m   = (const float*)d_in[24];
    const float* bn2v   = (const float*)d_in[25];
    const float* w_l2_w = (const float*)d_in[26];
    const float* w_l2_b = (const float*)d_in[27];
    float* out = (float*)d_out;

    // NOTE: knn moved to the 4th launch slot (the one ncu has been capturing)
    // so the next profile shows knn instead of qkv.
    pack_kernel<<<(NPTS + 255) / 256, 256>>>(p);
    prep_kernel<<<1, 256>>>(w_l2_w, bn1g, bn1b, bn1m, bn1v, bn2g, bn2b, bn2m, bn2v);
    qkv_gemm<<<dim3(CIN / 128, NPTS / 128, 3), 256>>>(x, w_q, b_q, w_k, b_k, w_v, b_v);
    knn_kernel<<<NPTS / 4, 128>>>();
    fused_kernel<<<NPTS, 256>>>(p, p_w1, p_b1, p_bn_g, p_bn_b, p_bn_m, p_bn_v,
                                p_w2, p_b2, w_l1_w, w_l1_b, w_l2_b, out);
}